// round 16
// baseline (speedup 1.0000x reference)
#include <cuda_runtime.h>
#include <math.h>

// ---------------- problem constants ----------------
#define Bc    128
#define BUFFc 64
#define STKc  48
#define HISTc 96
#define FCc   128
#define Uc    256
#define NOUTc 82
#define WDIMc 300
#define POSDc 50
#define EDINc 350
#define CADc  50
#define RDINc 306
#define NBLK  576
#define NITER 98
#define CSEQ  8
#define WST   68

// ---------------- device scratch ----------------
__device__ float g_buff_emb[Bc * BUFFc * FCc];
__device__ float g_comp_emb[Bc * STKc * 16 * FCc];
__device__ float g_stack_emb[Bc * STKc * FCc];

__device__ float g_zx0[Bc * STKc  * 1024];
__device__ float g_zx1[Bc * BUFFc * 1024];
__device__ float g_zx2[Bc * HISTc * 1024];

__device__ float g_p [3][2][Bc * 1024];
__device__ float g_c0[3][Bc * Uc];
__device__ float g_c1[3][Bc * Uc];
__device__ float g_h0[3][2][Bc * Uc];
__device__ float g_h1[3][2][Bc * Uc];

__device__ int g_perm[3][Bc];
__device__ int g_inv [3][Bc];
__device__ int g_lens[3][Bc];
__device__ int g_cnt [3][HISTc];

__device__ unsigned g_bar;

__device__ __forceinline__ float sigm(float x) {
    return __fdividef(1.0f, 1.0f + __expf(-x));
}
__device__ __forceinline__ float tanh_(float x) {
    return __fdividef(2.0f, 1.0f + __expf(-2.0f * x)) - 1.0f;
}

// ---------------- per-LSTM length sort (stable, descending) ----------------
__global__ void sort_kernel(const int* len0, const int* len1, const int* len2) {
    const int L = blockIdx.x;
    const int* len = (L == 0) ? len0 : (L == 1) ? len1 : len2;
    const int T = (L == 0) ? STKc : (L == 1) ? BUFFc : HISTc;
    __shared__ int sl[Bc];
    const int tid = threadIdx.x;
    sl[tid] = len[tid];
    __syncthreads();
    const int myl = sl[tid];
    int rank = 0;
    for (int b = 0; b < Bc; b++) {
        const int lb = sl[b];
        rank += (lb > myl) || (lb == myl && b < tid);
    }
    g_perm[L][rank] = tid;
    g_inv[L][tid] = rank;
    g_lens[L][rank] = myl;
    if (tid < T) {
        int c = 0;
        for (int b = 0; b < Bc; b++) c += (sl[b] > tid);
        g_cnt[L][tid] = c;
    }
}

// ---------------- persistent fused LSTM loop (smem-cached schedule tables) ----------------
struct PParams {
    const float* W0h[3];
    const float* b0[3];
    const float* W1a[3];
    const float* W1b[3];
    const float* b1[3];
};

__global__ void __launch_bounds__(128, 4) lstm_loop_kernel(PParams P) {
    const int tid = threadIdx.x;
    const int bid = blockIdx.x;

    __shared__ __align__(16) float xs[2][32][36];
    __shared__ __align__(16) float ws_raw[2 * 32 * WST];
    __shared__ int cnt_s [3 * HISTc];
    __shared__ int lens_s[3 * Bc];
    __shared__ int perm_s[3 * Bc];
#define WS(bf,k,c) ws_raw[(bf) * (32 * WST) + (k) * WST + (c)]

    for (int idx = tid; idx < 3 * HISTc; idx += 128) cnt_s[idx]  = ((const int*)g_cnt)[idx];
    for (int idx = tid; idx < 3 * Bc;    idx += 128) lens_s[idx] = ((const int*)g_lens)[idx];
    for (int idx = tid; idx < 3 * Bc;    idx += 128) perm_s[idx] = ((const int*)g_perm)[idx];
    __syncthreads();

    const int mi = tid & 7,  ni = tid >> 3;
    const int m0 = mi * 4,   n0t = ni * 4;
    const int xm = tid >> 2;
    const int xk4 = (tid & 3) * 4;
    const int wk = tid >> 4;
    const int wc4 = tid & 15;

    for (int i = 0; i < NITER; i++) {
        const int pr = (i + 1) & 1;
        const int pw = i & 1;

        int sfound = -1, local = 0, off = 0;
#pragma unroll
        for (int s = 0; s < 9; s++) {
            const int Ls = s / 3, kind = s - Ls * 3;
            const int Ts = (Ls == 0) ? STKc : (Ls == 1) ? BUFFc : HISTc;
            const int ts = i - kind;
            int nb = 0;
            if (ts >= 0 && ts < Ts) {
                const int cc = cnt_s[Ls * HISTc + ts];
                nb = (cc + 31) >> 5;
            }
            const int items = nb * 16;
            if (sfound < 0 && bid >= off && bid < off + items) {
                sfound = s; local = bid - off;
            }
            off += items;
        }

        if (sfound >= 0) {
            const int L = sfound / 3, kind = sfound - L * 3;
            const int Ts = (L == 0) ? STKc : (L == 1) ? BUFFc : HISTc;
            const int t = i - kind;
            const int bm = local >> 4, bu = local & 15;
            const int b0r = bm * 32;
            const int u0 = bu * 16;
            const int gcol = (wc4 >> 2) * 256 + u0 + (wc4 & 3) * 4;

            const float* src;
            const float* W;
            const float* extra = nullptr;
            const float* bias = nullptr;
            float* c = nullptr;
            float* h_out = nullptr;
            float* p_out = nullptr;
            bool gates;
            if (kind == 0) {
                gates = true;
                src = &g_h0[L][pr][0];
                W = P.W0h[L];
                bias = P.b0[L];
                c = &g_c0[L][0];
                h_out = &g_h0[L][pw][0];
            } else if (kind == 1) {
                gates = false;
                src = &g_h0[L][pr][0];
                W = P.W1a[L];
                p_out = &g_p[L][pr][0];
            } else {
                gates = true;
                src = &g_h1[L][pr][0];
                W = P.W1b[L];
                extra = &g_p[L][pw][0];
                bias = P.b1[L];
                c = &g_c1[L][0];
                h_out = &g_h1[L][pw][0];
            }

            float acc[4][4];
#pragma unroll
            for (int a = 0; a < 4; a++)
#pragma unroll
                for (int b = 0; b < 4; b++) acc[a][b] = 0.0f;

            const float* srow = src + (b0r + xm) * Uc;

            {
                float4 xa = __ldcg((const float4*)(srow + xk4));
                float4 xb = __ldcg((const float4*)(srow + xk4 + 16));
                xs[0][xk4 + 0][xm] = xa.x; xs[0][xk4 + 1][xm] = xa.y;
                xs[0][xk4 + 2][xm] = xa.z; xs[0][xk4 + 3][xm] = xa.w;
                xs[0][xk4 + 16][xm] = xb.x; xs[0][xk4 + 17][xm] = xb.y;
                xs[0][xk4 + 18][xm] = xb.z; xs[0][xk4 + 19][xm] = xb.w;
#pragma unroll
                for (int q = 0; q < 4; q++) {
                    const int kk = wk + 8 * q;
                    *(float4*)&WS(0, kk, wc4 * 4) =
                        *(const float4*)(W + (size_t)kk * 1024 + gcol);
                }
            }
            __syncthreads();

            int buf = 0;
#pragma unroll 1
            for (int kt = 0; kt < 8; kt++) {
                float4 xa, xb, wv0, wv1, wv2, wv3;
                const bool more = (kt < 7);
                if (more) {
                    const int k0 = (kt + 1) * 32;
                    xa = __ldcg((const float4*)(srow + k0 + xk4));
                    xb = __ldcg((const float4*)(srow + k0 + xk4 + 16));
                    const float* wrow = W + (size_t)(k0 + wk) * 1024 + gcol;
                    wv0 = *(const float4*)(wrow);
                    wv1 = *(const float4*)(wrow +  8 * 1024);
                    wv2 = *(const float4*)(wrow + 16 * 1024);
                    wv3 = *(const float4*)(wrow + 24 * 1024);
                }

                const float (*xsb)[36] = xs[buf];
#pragma unroll
                for (int kk = 0; kk < 32; kk++) {
                    const float4 x = *(const float4*)&xsb[kk][m0];
                    const float4 w = *(const float4*)&WS(buf, kk, n0t);
                    acc[0][0] = fmaf(x.x, w.x, acc[0][0]);
                    acc[0][1] = fmaf(x.x, w.y, acc[0][1]);
                    acc[0][2] = fmaf(x.x, w.z, acc[0][2]);
                    acc[0][3] = fmaf(x.x, w.w, acc[0][3]);
                    acc[1][0] = fmaf(x.y, w.x, acc[1][0]);
                    acc[1][1] = fmaf(x.y, w.y, acc[1][1]);
                    acc[1][2] = fmaf(x.y, w.z, acc[1][2]);
                    acc[1][3] = fmaf(x.y, w.w, acc[1][3]);
                    acc[2][0] = fmaf(x.z, w.x, acc[2][0]);
                    acc[2][1] = fmaf(x.z, w.y, acc[2][1]);
                    acc[2][2] = fmaf(x.z, w.z, acc[2][2]);
                    acc[2][3] = fmaf(x.z, w.w, acc[2][3]);
                    acc[3][0] = fmaf(x.w, w.x, acc[3][0]);
                    acc[3][1] = fmaf(x.w, w.y, acc[3][1]);
                    acc[3][2] = fmaf(x.w, w.z, acc[3][2]);
                    acc[3][3] = fmaf(x.w, w.w, acc[3][3]);
                }

                if (more) {
                    const int nb2 = buf ^ 1;
                    xs[nb2][xk4 + 0][xm] = xa.x; xs[nb2][xk4 + 1][xm] = xa.y;
                    xs[nb2][xk4 + 2][xm] = xa.z; xs[nb2][xk4 + 3][xm] = xa.w;
                    xs[nb2][xk4 + 16][xm] = xb.x; xs[nb2][xk4 + 17][xm] = xb.y;
                    xs[nb2][xk4 + 18][xm] = xb.z; xs[nb2][xk4 + 19][xm] = xb.w;
                    *(float4*)&WS(nb2, wk +  0, wc4 * 4) = wv0;
                    *(float4*)&WS(nb2, wk +  8, wc4 * 4) = wv1;
                    *(float4*)&WS(nb2, wk + 16, wc4 * 4) = wv2;
                    *(float4*)&WS(nb2, wk + 24, wc4 * 4) = wv3;
                    __syncthreads();
                    buf = nb2;
                }
            }

            if (!gates) {
                const int gcolS = (n0t >> 4) * 256 + u0 + (n0t & 15);
#pragma unroll
                for (int a = 0; a < 4; a++) {
                    __stcg((float4*)(p_out + (size_t)(b0r + m0 + a) * 1024 + gcolS),
                           make_float4(acc[a][0], acc[a][1], acc[a][2], acc[a][3]));
                }
            } else {
                __syncthreads();
                float* zt = ws_raw;
#pragma unroll
                for (int cc = 0; cc < 4; cc++)
#pragma unroll
                    for (int a = 0; a < 4; a++)
                        zt[(n0t + cc) * 33 + (m0 + a)] = acc[a][cc];
                __syncthreads();

                const int uu = tid & 15;
                const int bq = tid >> 4;
                const int colu = u0 + uu;
                const float bi = bias[colu];
                const float bj = bias[256 + colu];
                const float bf = bias[512 + colu];
                const float bo = bias[768 + colu];
                const float* zxbase = (L == 0) ? g_zx0 : (L == 1) ? g_zx1 : g_zx2;

#pragma unroll
                for (int q = 0; q < 4; q++) {
                    const int bl = bq + 8 * q;
                    const int j = b0r + bl;
                    if (t < lens_s[L * Bc + j]) {
                        const float* er;
                        if (kind == 0)
                            er = zxbase + ((size_t)perm_s[L * Bc + j] * Ts + t) * 1024;
                        else
                            er = extra + (size_t)j * 1024;
                        const int gidx = j * Uc + colu;
                        float g0 = zt[(  0 + uu) * 33 + bl] + bi + __ldcg(&er[colu]);
                        float g1 = zt[( 16 + uu) * 33 + bl] + bj + __ldcg(&er[256 + colu]);
                        float g2 = zt[( 32 + uu) * 33 + bl] + bf + __ldcg(&er[512 + colu]);
                        float g3 = zt[( 48 + uu) * 33 + bl] + bo + __ldcg(&er[768 + colu]);
                        const float cn = __ldcg(&c[gidx]) * sigm(g2 + 1.0f)
                                       + sigm(g0) * tanh_(g1);
                        const float hn = tanh_(cn) * sigm(g3);
                        __stcg(&c[gidx], cn);
                        __stcg(&h_out[gidx], hn);
                    }
                }
            }
        }

        __syncthreads();
        __threadfence();
        if (tid == 0) {
            atomicAdd(&g_bar, 1u);
            const unsigned target = (unsigned)NBLK * (unsigned)(i + 1);
            volatile unsigned* vb = &g_bar;
            while (*vb < target) __nanosleep(32);
        }
        __syncthreads();
    }
#undef WS
}

// ---------------- x-projection precompute (3-job batched, masked-block skip) ----------------
struct XJob { const float* x; const int* ids; const float* tab;
              const float* W; float* zx; const int* len; int rows, Din, T; };
struct XJobs { XJob j[3]; };

__global__ void xproj_kernel(XJobs jobs) {
    const XJob J = jobs.j[blockIdx.y];
    const int bm = blockIdx.x % 384;
    const int bn = blockIdx.x / 384;
    const int r0 = bm * 32;
    if (r0 >= J.rows) return;
    const int tid = threadIdx.x;

    int pred = 0;
    if (tid < 32) {
        const int r = r0 + tid;
        const int bb = r / J.T;
        const int tt = r - bb * J.T;
        pred = (tt < J.len[bb]);
    }
    if (!__syncthreads_or(pred)) return;

    const int n0 = bn * 128;
    __shared__ __align__(16) float xs[32][36];
    __shared__ __align__(16) float ws[32][128];
    const int mi = tid & 7, ni = tid >> 3;
    const int m0 = mi * 4, n0t = ni * 4;
    const int xm = tid >> 3, xk = (tid & 7) * 4;
    const int wc = (tid & 31) * 4, wk = tid >> 5;

    float acc[4][4];
#pragma unroll
    for (int a = 0; a < 4; a++)
#pragma unroll
        for (int b = 0; b < 4; b++) acc[a][b] = 0.0f;

    const int r = r0 + xm;
    const float* srow = J.ids ? (J.tab + (size_t)J.ids[r] * J.Din)
                              : (J.x + (size_t)r * J.Din);

    const int nk = (J.Din + 31) >> 5;
    for (int kt = 0; kt < nk; kt++) {
        const int k0 = kt * 32;
        __syncthreads();
#pragma unroll
        for (int j = 0; j < 4; j++) {
            const int k = k0 + xk + j;
            xs[xk + j][xm] = (k < J.Din) ? srow[k] : 0.0f;
        }
#pragma unroll
        for (int q = 0; q < 4; q++) {
            const int kk = wk + 8 * q, k = k0 + kk;
            float4 wv = make_float4(0.f, 0.f, 0.f, 0.f);
            if (k < J.Din)
                wv = *(const float4*)(J.W + (size_t)k * 1024 + n0 + wc);
            *(float4*)&ws[kk][wc] = wv;
        }
        __syncthreads();
#pragma unroll 8
        for (int kk = 0; kk < 32; kk++) {
            const float4 x = *(const float4*)&xs[kk][m0];
            const float4 w = *(const float4*)&ws[kk][n0t];
            acc[0][0] = fmaf(x.x, w.x, acc[0][0]);
            acc[0][1] = fmaf(x.x, w.y, acc[0][1]);
            acc[0][2] = fmaf(x.x, w.z, acc[0][2]);
            acc[0][3] = fmaf(x.x, w.w, acc[0][3]);
            acc[1][0] = fmaf(x.y, w.x, acc[1][0]);
            acc[1][1] = fmaf(x.y, w.y, acc[1][1]);
            acc[1][2] = fmaf(x.y, w.z, acc[1][2]);
            acc[1][3] = fmaf(x.y, w.w, acc[1][3]);
            acc[2][0] = fmaf(x.z, w.x, acc[2][0]);
            acc[2][1] = fmaf(x.z, w.y, acc[2][1]);
            acc[2][2] = fmaf(x.z, w.z, acc[2][2]);
            acc[2][3] = fmaf(x.z, w.w, acc[2][3]);
            acc[3][0] = fmaf(x.w, w.x, acc[3][0]);
            acc[3][1] = fmaf(x.w, w.y, acc[3][1]);
            acc[3][2] = fmaf(x.w, w.z, acc[3][2]);
            acc[3][3] = fmaf(x.w, w.w, acc[3][3]);
        }
    }
#pragma unroll
    for (int a = 0; a < 4; a++) {
        *(float4*)(J.zx + (size_t)(r0 + m0 + a) * 1024 + n0 + n0t) =
            make_float4(acc[a][0], acc[a][1], acc[a][2], acc[a][3]);
    }
}

// ---------------- embedding v3 (unchanged) ----------------
__global__ void __launch_bounds__(128) embed_kernel(
    const int* __restrict__ word_ids,
    const int* __restrict__ pos_ids,
    const float* __restrict__ w_emb,
    const float* __restrict__ p_emb,
    const float* __restrict__ W,
    const float* __restrict__ bias,
    float* __restrict__ out,
    int nrows,
    const int* __restrict__ len,
    int per_b, int per_item)
{
    const int r0 = blockIdx.x * 8;
    {
        const int b = r0 / per_b;
        const int item = (r0 - b * per_b) / per_item;
        if (item >= len[b]) return;
    }
    __shared__ __align__(16) float xs[EDINc][10];
    __shared__ int wid_s[8], pid_s[8];
    const int tid = threadIdx.x;

    if (tid < 8) {
        int row = r0 + tid;
        wid_s[tid] = (row < nrows) ? word_ids[row] : 0;
        pid_s[tid] = (row < nrows) ? pos_ids[row] : 0;
    }
    __syncthreads();

    for (int idx = tid; idx < 8 * EDINc; idx += 128) {
        int r = idx / EDINc, k = idx - r * EDINc;
        float v;
        if (k < WDIMc) v = w_emb[wid_s[r] * WDIMc + k];
        else           v = p_emb[pid_s[r] * POSDc + (k - WDIMc)];
        xs[k][r] = v;
    }
    __syncthreads();

    const int ri = tid >> 5;
    const int s0 = 2 * ri;
    const int n0 = (tid & 31) * 4;
    const float4 bv = *(const float4*)(bias + n0);
    const float* Wn = W + n0;

    float a00 = 0.f, a01 = 0.f, a02 = 0.f, a03 = 0.f;
    float a10 = 0.f, a11 = 0.f, a12 = 0.f, a13 = 0.f;

    float4 w0 = *(const float4*)(Wn + 0 * FCc);
    float4 w1 = *(const float4*)(Wn + 1 * FCc);
    float4 w2 = *(const float4*)(Wn + 2 * FCc);
    float4 w3 = *(const float4*)(Wn + 3 * FCc);
#pragma unroll 1
    for (int k = 0; k < 348; k += 4) {
        float4 p0, p1, p2, p3;
        p0 = (k + 4 < EDINc) ? *(const float4*)(Wn + (size_t)(k + 4) * FCc) : w0;
        p1 = (k + 5 < EDINc) ? *(const float4*)(Wn + (size_t)(k + 5) * FCc) : w1;
        p2 = (k + 6 < EDINc) ? *(const float4*)(Wn + (size_t)(k + 6) * FCc) : w2;
        p3 = (k + 7 < EDINc) ? *(const float4*)(Wn + (size_t)(k + 7) * FCc) : w3;
        const float2 x0 = *(const float2*)&xs[k + 0][s0];
        const float2 x1 = *(const float2*)&xs[k + 1][s0];
        const float2 x2 = *(const float2*)&xs[k + 2][s0];
        const float2 x3 = *(const float2*)&xs[k + 3][s0];
        a00 = fmaf(x0.x, w0.x, a00); a01 = fmaf(x0.x, w0.y, a01);
        a02 = fmaf(x0.x, w0.z, a02); a03 = fmaf(x0.x, w0.w, a03);
        a10 = fmaf(x0.y, w0.x, a10); a11 = fmaf(x0.y, w0.y, a11);
        a12 = fmaf(x0.y, w0.z, a12); a13 = fmaf(x0.y, w0.w, a13);
        a00 = fmaf(x1.x, w1.x, a00); a01 = fmaf(x1.x, w1.y, a01);
        a02 = fmaf(x1.x, w1.z, a02); a03 = fmaf(x1.x, w1.w, a03);
        a10 = fmaf(x1.y, w1.x, a10); a11 = fmaf(x1.y, w1.y, a11);
        a12 = fmaf(x1.y, w1.z, a12); a13 = fmaf(x1.y, w1.w, a13);
        a00 = fmaf(x2.x, w2.x, a00); a01 = fmaf(x2.x, w2.y, a01);
        a02 = fmaf(x2.x, w2.z, a02); a03 = fmaf(x2.x, w2.w, a03);
        a10 = fmaf(x2.y, w2.x, a10); a11 = fmaf(x2.y, w2.y, a11);
        a12 = fmaf(x2.y, w2.z, a12); a13 = fmaf(x2.y, w2.w, a13);
        a00 = fmaf(x3.x, w3.x, a00); a01 = fmaf(x3.x, w3.y, a01);
        a02 = fmaf(x3.x, w3.z, a02); a03 = fmaf(x3.x, w3.w, a03);
        a10 = fmaf(x3.y, w3.x, a10); a11 = fmaf(x3.y, w3.y, a11);
        a12 = fmaf(x3.y, w3.z, a12); a13 = fmaf(x3.y, w3.w, a13);
        w0 = p0; w1 = p1; w2 = p2; w3 = p3;
    }
    {
        const float2 x0 = *(const float2*)&xs[348][s0];
        const float2 x1 = *(const float2*)&xs[349][s0];
        a00 = fmaf(x0.x, w0.x, a00); a01 = fmaf(x0.x, w0.y, a01);
        a02 = fmaf(x0.x, w0.z, a02); a03 = fmaf(x0.x, w0.w, a03);
        a10 = fmaf(x0.y, w0.x, a10); a11 = fmaf(x0.y, w0.y, a11);
        a12 = fmaf(x0.y, w0.z, a12); a13 = fmaf(x0.y, w0.w, a13);
        a00 = fmaf(x1.x, w1.x, a00); a01 = fmaf(x1.x, w1.y, a01);
        a02 = fmaf(x1.x, w1.z, a02); a03 = fmaf(x1.x, w1.w, a03);
        a10 = fmaf(x1.y, w1.x, a10); a11 = fmaf(x1.y, w1.y, a11);
        a12 = fmaf(x1.y, w1.z, a12); a13 = fmaf(x1.y, w1.w, a13);
    }

    const int rowA = r0 + s0, rowB = r0 + s0 + 1;
    if (rowA < nrows)
        *(float4*)(out + (size_t)rowA * FCc + n0) = make_float4(
            fmaxf(a00 + bv.x, 0.f), fmaxf(a01 + bv.y, 0.f),
            fmaxf(a02 + bv.z, 0.f), fmaxf(a03 + bv.w, 0.f));
    if (rowB < nrows)
        *(float4*)(out + (size_t)rowB * FCc + n0) = make_float4(
            fmaxf(a10 + bv.x, 0.f), fmaxf(a11 + bv.y, 0.f),
            fmaxf(a12 + bv.z, 0.f), fmaxf(a13 + bv.w, 0.f));
}

// ---------------- compose v5: 256 threads, warp-per-seq, depth-8 W prefetch ----------------
__global__ void __launch_bounds__(256) compose_kernel(
    const int* __restrict__ comp_word_id,
    const float* __restrict__ comp_emb,
    const int* __restrict__ comp_action_id,
    const int* __restrict__ comp_action_len,
    const float* __restrict__ a_emb,
    const float* __restrict__ rec_W,
    const float* __restrict__ rec_b,
    const int* __restrict__ stack_len,
    float* __restrict__ stack_emb)
{
    const int seq0 = blockIdx.x * CSEQ;
    {
        const int b = seq0 / STKc;
        const int stk0 = seq0 - b * STKc;
        if (stk0 >= stack_len[b]) return;
    }
    const int tid = threadIdx.x;

    __shared__ float vals[8][CSEQ][FCc];
    __shared__ __align__(16) float xs[RDINc][10];
    __shared__ int wid[CSEQ][16];
    __shared__ int act[CSEQ][8];
    __shared__ int alen[CSEQ];
    __shared__ signed char ihs[CSEQ][8], idds[CSEQ][8];

    {
        if (tid < 128) {
            const int ss = tid >> 4, slot = tid & 15;
            wid[ss][slot] = comp_word_id[(seq0 + ss) * 16 + slot];
        }
        if (tid >= 128 && tid < 128 + CSEQ * 8) {
            const int q = tid - 128;
            const int s2 = q >> 3, n = q & 7;
            act[s2][n] = comp_action_id[(seq0 + s2) * 8 + n];
        }
        if (tid >= 192 && tid < 192 + CSEQ)
            alen[tid - 192] = comp_action_len[seq0 + (tid - 192)];
    }
    __syncthreads();
    if (tid < CSEQ * 8) {
        const int ss = tid >> 3, n = tid & 7;
        const int hn = wid[ss][2 * n], dn = wid[ss][2 * n + 1];
        int ih = -1, idd = -1;
        for (int m = 0; m < n; m++) {
            const int hm = wid[ss][2 * m];
            if (hm == hn) ih = m;
            if (hm == dn) idd = m;
        }
        ihs[ss][n] = (signed char)ih;
        idds[ss][n] = (signed char)idd;
    }
    __syncthreads();

    const int mi = tid >> 5;          // warp = seq
    const int ni = tid & 31;          // lane = 4-col group
    const int n0 = ni * 4;
    const float4 bn = *(const float4*)(rec_b + n0);
    const float* Wn = rec_W + n0;

    for (int n = 0; n < 8; n++) {
        // ---- stage X[k][s]: 256 threads cover (ss, k) ----
#pragma unroll
        for (int ss2 = 0; ss2 < CSEQ; ss2 += 2) {
            const int ss = ss2 + (tid >> 7);       // 2 seqs per pass
            const int kb = tid & 127;
            const int ih = ihs[ss][n], idd = idds[ss][n];
            const int an = act[ss][n];
#pragma unroll
            for (int j = 0; j < 3; j++) {
                const int k = kb + j * 128;
                if (k < RDINc) {
                    float v;
                    if (k < FCc) {
                        v = (ih >= 0) ? vals[ih][ss][k]
                                      : comp_emb[((size_t)(seq0 + ss) * 16 + 2 * n) * FCc + k];
                    } else if (k < FCc + CADc) {
                        v = a_emb[an * CADc + (k - FCc)];
                    } else {
                        const int kk = k - (FCc + CADc);
                        v = (idd >= 0) ? vals[idd][ss][kk]
                                       : comp_emb[((size_t)(seq0 + ss) * 16 + 2 * n + 1) * FCc + kk];
                    }
                    xs[k][ss] = v;
                }
            }
        }
        __syncthreads();

        // ---- GEMM: warp mi computes seq mi's 4 cols; depth-8 W prefetch ----
        float a0 = 0.f, a1 = 0.f, a2 = 0.f, a3 = 0.f;

        float4 w[8];
#pragma unroll
        for (int j = 0; j < 8; j++)
            w[j] = *(const float4*)(Wn + (size_t)j * FCc);

#pragma unroll 1
        for (int k = 0; k < 296; k += 8) {
            float4 p[8];
#pragma unroll
            for (int j = 0; j < 8; j++)
                p[j] = *(const float4*)(Wn + (size_t)(k + 8 + j) * FCc);
#pragma unroll
            for (int j = 0; j < 8; j++) {
                const float x = xs[k + j][mi];
                a0 = fmaf(x, w[j].x, a0); a1 = fmaf(x, w[j].y, a1);
                a2 = fmaf(x, w[j].z, a2); a3 = fmaf(x, w[j].w, a3);
            }
#pragma unroll
            for (int j = 0; j < 8; j++) w[j] = p[j];
        }
#pragma unroll
        for (int j = 0; j < 8; j++) {
            const float x = xs[296 + j][mi];
            a0 = fmaf(x, w[j].x, a0); a1 = fmaf(x, w[j].y, a1);
            a2 = fmaf(x, w[j].z, a2); a3 = fmaf(x, w[j].w, a3);
        }
#pragma unroll
        for (int j = 0; j < 2; j++) {
            const float4 wt = *(const float4*)(Wn + (size_t)(304 + j) * FCc);
            const float x = xs[304 + j][mi];
            a0 = fmaf(x, wt.x, a0); a1 = fmaf(x, wt.y, a1);
            a2 = fmaf(x, wt.z, a2); a3 = fmaf(x, wt.w, a3);
        }

        *(float4*)&vals[n][mi][n0] = make_float4(
            tanhf(a0 + bn.x), tanhf(a1 + bn.y), tanhf(a2 + bn.z), tanhf(a3 + bn.w));
        __syncthreads();
    }

    // ---- outputs: 1024 elems by 256 threads ----
#pragma unroll
    for (int q = 0; q < 4; q++) {
        const int idx = tid + q * 256;
        const int ss = idx >> 7, col = idx & 127;
        const int al = alen[ss];
        const float v = (al == 0)
            ? comp_emb[(size_t)(seq0 + ss) * 16 * FCc + col]
            : vals[al - 1][ss][col];
        stack_emb[(size_t)(seq0 + ss) * FCc + col] = v;
    }
}

// ---------------- output head ----------------
__global__ void final_kernel(const int* __restrict__ l0,
                             const int* __restrict__ l1,
                             const int* __restrict__ l2,
                             const float* __restrict__ fW,
                             const float* __restrict__ fb,
                             float* __restrict__ out) {
    const int b = blockIdx.x;
    const int tid = threadIdx.x;
    __shared__ float hcat[3 * Uc];
    for (int idx = tid; idx < 3 * Uc; idx += 128) {
        const int L = idx >> 8;
        const int col = idx & 255;
        const int len = ((L == 0) ? l0 : (L == 1) ? l1 : l2)[b];
        const int j = g_inv[L][b];
        hcat[idx] = g_h1[L][(len - 1) & 1][j * Uc + col];
    }
    __syncthreads();
    if (tid < NOUTc) {
        float acc = fb[tid];
#pragma unroll 2
        for (int k = 0; k < 3 * Uc; k++) acc = fmaf(hcat[k], fW[k * NOUTc + tid], acc);
        out[b * NOUTc + tid] = acc;
    }
}

// ---------------- host driver (single stream) ----------------
extern "C" void kernel_launch(void* const* d_in, const int* in_sizes, int n_in,
                              void* d_out, int out_size) {
    const int*   buff_word_id   = (const int*)d_in[0];
    const int*   buff_pos_id    = (const int*)d_in[1];
    const int*   comp_word_id   = (const int*)d_in[2];
    const int*   comp_pos_id    = (const int*)d_in[3];
    const int*   comp_action_id = (const int*)d_in[4];
    const int*   comp_action_len= (const int*)d_in[5];
    const int*   history_action_id = (const int*)d_in[6];
    const int*   stack_length   = (const int*)d_in[7];
    const int*   buff_length    = (const int*)d_in[8];
    const int*   history_action_length = (const int*)d_in[9];
    const float* p_emb      = (const float*)d_in[10];
    const float* comp_a_emb = (const float*)d_in[11];
    const float* hist_a_emb = (const float*)d_in[12];
    const float* w_emb      = (const float*)d_in[13];
    const float* emb_W      = (const float*)d_in[14];
    const float* emb_b      = (const float*)d_in[15];
    const float* rec_W      = (const float*)d_in[16];
    const float* rec_b      = (const float*)d_in[17];
    const float* W0s[3] = { (const float*)d_in[18], (const float*)d_in[22], (const float*)d_in[26] };
    const float* b0s[3] = { (const float*)d_in[19], (const float*)d_in[23], (const float*)d_in[27] };
    const float* W1s[3] = { (const float*)d_in[20], (const float*)d_in[24], (const float*)d_in[28] };
    const float* b1s[3] = { (const float*)d_in[21], (const float*)d_in[25], (const float*)d_in[29] };
    const float* fW  = (const float*)d_in[30];
    const float* fb  = (const float*)d_in[31];
    float* out = (float*)d_out;

    float *buff_emb_p, *comp_emb_p, *stack_emb_p;
    float *zx0_p, *zx1_p, *zx2_p;
    float *c0_p, *c1_p, *h0_p, *h1_p;
    unsigned* bar_p;
    cudaGetSymbolAddress((void**)&buff_emb_p,  g_buff_emb);
    cudaGetSymbolAddress((void**)&comp_emb_p,  g_comp_emb);
    cudaGetSymbolAddress((void**)&stack_emb_p, g_stack_emb);
    cudaGetSymbolAddress((void**)&zx0_p, g_zx0);
    cudaGetSymbolAddress((void**)&zx1_p, g_zx1);
    cudaGetSymbolAddress((void**)&zx2_p, g_zx2);
    cudaGetSymbolAddress((void**)&c0_p, g_c0);
    cudaGetSymbolAddress((void**)&c1_p, g_c1);
    cudaGetSymbolAddress((void**)&h0_p, g_h0);
    cudaGetSymbolAddress((void**)&h1_p, g_h1);
    cudaGetSymbolAddress((void**)&bar_p, g_bar);

    const size_t SB = (size_t)Bc * Uc;

    cudaMemsetAsync(bar_p, 0, sizeof(unsigned));
    cudaMemsetAsync(c0_p, 0, 3 * SB * sizeof(float));
    cudaMemsetAsync(c1_p, 0, 3 * SB * sizeof(float));
    cudaMemsetAsync(h0_p, 0, 3 * 2 * SB * sizeof(float));
    cudaMemsetAsync(h1_p, 0, 3 * 2 * SB * sizeof(float));

    // length sort + per-step active counts
    sort_kernel<<<3, 128>>>(stack_length, buff_length, history_action_length);

    // embeddings (dead-block skipping)
    const int nbuff = Bc * BUFFc;
    embed_kernel<<<(nbuff + 7) / 8, 128>>>(buff_word_id, buff_pos_id, w_emb, p_emb,
                                           emb_W, emb_b, buff_emb_p, nbuff,
                                           buff_length, BUFFc, 1);
    const int ncomp = Bc * STKc * 16;
    embed_kernel<<<(ncomp + 7) / 8, 128>>>(comp_word_id, comp_pos_id, w_emb, p_emb,
                                           emb_W, emb_b, comp_emb_p, ncomp,
                                           stack_length, STKc * 16, 16);

    // recursive compose (v5: 256 threads, warp-per-seq)
    compose_kernel<<<Bc * STKc / CSEQ, 256>>>(comp_word_id, comp_emb_p,
                                              comp_action_id, comp_action_len,
                                              comp_a_emb, rec_W, rec_b,
                                              stack_length, stack_emb_p);

    // x-projections for layer0
    {
        XJobs xj;
        xj.j[0] = XJob{ stack_emb_p, nullptr, nullptr, W0s[0], zx0_p,
                        stack_length, Bc * STKc,  FCc, STKc };
        xj.j[1] = XJob{ buff_emb_p,  nullptr, nullptr, W0s[1], zx1_p,
                        buff_length, Bc * BUFFc, FCc, BUFFc };
        xj.j[2] = XJob{ nullptr, history_action_id, hist_a_emb, W0s[2], zx2_p,
                        history_action_length, Bc * HISTc, 50, HISTc };
        xproj_kernel<<<dim3(384 * 8, 3), 256>>>(xj);
    }

    // persistent fused loop
    {
        PParams P;
        for (int L = 0; L < 3; L++) {
            const int din = (L == 2) ? 50 : FCc;
            P.W0h[L] = W0s[L] + (size_t)din * 1024;
            P.b0[L]  = b0s[L];
            P.W1a[L] = W1s[L];
            P.W1b[L] = W1s[L] + (size_t)256 * 1024;
            P.b1[L]  = b1s[L];
        }
        lstm_loop_kernel<<<NBLK, 128>>>(P);
    }

    // output head
    final_kernel<<<Bc, 128>>>(stack_length, buff_length, history_action_length,
                              fW, fb, out);
}

// round 17
// speedup vs baseline: 1.6510x; 1.6510x over previous
#include <cuda_runtime.h>
#include <math.h>

// ---------------- problem constants ----------------
#define Bc    128
#define BUFFc 64
#define STKc  48
#define HISTc 96
#define FCc   128
#define Uc    256
#define NOUTc 82
#define WDIMc 300
#define POSDc 50
#define EDINc 350
#define CADc  50
#define RDINc 306
#define NBLK  576
#define NITER 98
#define CSEQ  8
#define WST   68

// ---------------- device scratch ----------------
__device__ float g_buff_emb[Bc * BUFFc * FCc];
__device__ float g_comp_emb[Bc * STKc * 16 * FCc];
__device__ float g_stack_emb[Bc * STKc * FCc];

__device__ float g_zx0[Bc * STKc  * 1024];
__device__ float g_zx1[Bc * BUFFc * 1024];
__device__ float g_zx2[Bc * HISTc * 1024];

__device__ float g_p [3][2][Bc * 1024];
__device__ float g_c0[3][Bc * Uc];
__device__ float g_c1[3][Bc * Uc];
__device__ float g_h0[3][2][Bc * Uc];
__device__ float g_h1[3][2][Bc * Uc];

__device__ int g_perm[3][Bc];
__device__ int g_inv [3][Bc];
__device__ int g_lens[3][Bc];
__device__ int g_cnt [3][HISTc];

__device__ unsigned g_bar;

__device__ __forceinline__ float sigm(float x) {
    return __fdividef(1.0f, 1.0f + __expf(-x));
}
__device__ __forceinline__ float tanh_(float x) {
    return __fdividef(2.0f, 1.0f + __expf(-2.0f * x)) - 1.0f;
}

// ---------------- per-LSTM length sort (stable, descending) ----------------
__global__ void sort_kernel(const int* len0, const int* len1, const int* len2) {
    const int L = blockIdx.x;
    const int* len = (L == 0) ? len0 : (L == 1) ? len1 : len2;
    const int T = (L == 0) ? STKc : (L == 1) ? BUFFc : HISTc;
    __shared__ int sl[Bc];
    const int tid = threadIdx.x;
    sl[tid] = len[tid];
    __syncthreads();
    const int myl = sl[tid];
    int rank = 0;
    for (int b = 0; b < Bc; b++) {
        const int lb = sl[b];
        rank += (lb > myl) || (lb == myl && b < tid);
    }
    g_perm[L][rank] = tid;
    g_inv[L][tid] = rank;
    g_lens[L][rank] = myl;
    if (tid < T) {
        int c = 0;
        for (int b = 0; b < Bc; b++) c += (sl[b] > tid);
        g_cnt[L][tid] = c;
    }
}

// ---------------- persistent fused LSTM loop (gates-prefetch epilogue) ----------------
struct PParams {
    const float* W0h[3];
    const float* b0[3];
    const float* W1a[3];
    const float* W1b[3];
    const float* b1[3];
};

__global__ void __launch_bounds__(128, 4) lstm_loop_kernel(PParams P) {
    const int tid = threadIdx.x;
    const int bid = blockIdx.x;

    __shared__ __align__(16) float xs[2][32][36];
    __shared__ __align__(16) float ws_raw[2 * 32 * WST];
    __shared__ int cnt_s [3 * HISTc];
    __shared__ int lens_s[3 * Bc];
    __shared__ int perm_s[3 * Bc];
#define WS(bf,k,c) ws_raw[(bf) * (32 * WST) + (k) * WST + (c)]

    for (int idx = tid; idx < 3 * HISTc; idx += 128) cnt_s[idx]  = ((const int*)g_cnt)[idx];
    for (int idx = tid; idx < 3 * Bc;    idx += 128) lens_s[idx] = ((const int*)g_lens)[idx];
    for (int idx = tid; idx < 3 * Bc;    idx += 128) perm_s[idx] = ((const int*)g_perm)[idx];
    __syncthreads();

    const int mi = tid & 7,  ni = tid >> 3;
    const int m0 = mi * 4,   n0t = ni * 4;
    const int xm = tid >> 2;
    const int xk4 = (tid & 3) * 4;
    const int wk = tid >> 4;
    const int wc4 = tid & 15;

    for (int i = 0; i < NITER; i++) {
        const int pr = (i + 1) & 1;
        const int pw = i & 1;

        int sfound = -1, local = 0, off = 0;
#pragma unroll
        for (int s = 0; s < 9; s++) {
            const int Ls = s / 3, kind = s - Ls * 3;
            const int Ts = (Ls == 0) ? STKc : (Ls == 1) ? BUFFc : HISTc;
            const int ts = i - kind;
            int nb = 0;
            if (ts >= 0 && ts < Ts) {
                const int cc = cnt_s[Ls * HISTc + ts];
                nb = (cc + 31) >> 5;
            }
            const int items = nb * 16;
            if (sfound < 0 && bid >= off && bid < off + items) {
                sfound = s; local = bid - off;
            }
            off += items;
        }

        if (sfound >= 0) {
            const int L = sfound / 3, kind = sfound - L * 3;
            const int Ts = (L == 0) ? STKc : (L == 1) ? BUFFc : HISTc;
            const int t = i - kind;
            const int bm = local >> 4, bu = local & 15;
            const int b0r = bm * 32;
            const int u0 = bu * 16;
            const int gcol = (wc4 >> 2) * 256 + u0 + (wc4 & 3) * 4;

            const float* src;
            const float* W;
            const float* extra = nullptr;
            const float* bias = nullptr;
            float* c = nullptr;
            float* h_out = nullptr;
            float* p_out = nullptr;
            bool gates;
            if (kind == 0) {
                gates = true;
                src = &g_h0[L][pr][0];
                W = P.W0h[L];
                bias = P.b0[L];
                c = &g_c0[L][0];
                h_out = &g_h0[L][pw][0];
            } else if (kind == 1) {
                gates = false;
                src = &g_h0[L][pr][0];
                W = P.W1a[L];
                p_out = &g_p[L][pr][0];
            } else {
                gates = true;
                src = &g_h1[L][pr][0];
                W = P.W1b[L];
                extra = &g_p[L][pw][0];
                bias = P.b1[L];
                c = &g_c1[L][0];
                h_out = &g_h1[L][pw][0];
            }

            float acc[4][4];
#pragma unroll
            for (int a = 0; a < 4; a++)
#pragma unroll
                for (int b = 0; b < 4; b++) acc[a][b] = 0.0f;

            const float* srow = src + (b0r + xm) * Uc;

            {
                float4 xa = __ldcg((const float4*)(srow + xk4));
                float4 xb = __ldcg((const float4*)(srow + xk4 + 16));
                xs[0][xk4 + 0][xm] = xa.x; xs[0][xk4 + 1][xm] = xa.y;
                xs[0][xk4 + 2][xm] = xa.z; xs[0][xk4 + 3][xm] = xa.w;
                xs[0][xk4 + 16][xm] = xb.x; xs[0][xk4 + 17][xm] = xb.y;
                xs[0][xk4 + 18][xm] = xb.z; xs[0][xk4 + 19][xm] = xb.w;
#pragma unroll
                for (int q = 0; q < 4; q++) {
                    const int kk = wk + 8 * q;
                    *(float4*)&WS(0, kk, wc4 * 4) =
                        *(const float4*)(W + (size_t)kk * 1024 + gcol);
                }
            }
            __syncthreads();

            int buf = 0;
#pragma unroll 1
            for (int kt = 0; kt < 8; kt++) {
                float4 xa, xb, wv0, wv1, wv2, wv3;
                const bool more = (kt < 7);
                if (more) {
                    const int k0 = (kt + 1) * 32;
                    xa = __ldcg((const float4*)(srow + k0 + xk4));
                    xb = __ldcg((const float4*)(srow + k0 + xk4 + 16));
                    const float* wrow = W + (size_t)(k0 + wk) * 1024 + gcol;
                    wv0 = *(const float4*)(wrow);
                    wv1 = *(const float4*)(wrow +  8 * 1024);
                    wv2 = *(const float4*)(wrow + 16 * 1024);
                    wv3 = *(const float4*)(wrow + 24 * 1024);
                }

                const float (*xsb)[36] = xs[buf];
#pragma unroll
                for (int kk = 0; kk < 32; kk++) {
                    const float4 x = *(const float4*)&xsb[kk][m0];
                    const float4 w = *(const float4*)&WS(buf, kk, n0t);
                    acc[0][0] = fmaf(x.x, w.x, acc[0][0]);
                    acc[0][1] = fmaf(x.x, w.y, acc[0][1]);
                    acc[0][2] = fmaf(x.x, w.z, acc[0][2]);
                    acc[0][3] = fmaf(x.x, w.w, acc[0][3]);
                    acc[1][0] = fmaf(x.y, w.x, acc[1][0]);
                    acc[1][1] = fmaf(x.y, w.y, acc[1][1]);
                    acc[1][2] = fmaf(x.y, w.z, acc[1][2]);
                    acc[1][3] = fmaf(x.y, w.w, acc[1][3]);
                    acc[2][0] = fmaf(x.z, w.x, acc[2][0]);
                    acc[2][1] = fmaf(x.z, w.y, acc[2][1]);
                    acc[2][2] = fmaf(x.z, w.z, acc[2][2]);
                    acc[2][3] = fmaf(x.z, w.w, acc[2][3]);
                    acc[3][0] = fmaf(x.w, w.x, acc[3][0]);
                    acc[3][1] = fmaf(x.w, w.y, acc[3][1]);
                    acc[3][2] = fmaf(x.w, w.z, acc[3][2]);
                    acc[3][3] = fmaf(x.w, w.w, acc[3][3]);
                }

                if (more) {
                    const int nb2 = buf ^ 1;
                    xs[nb2][xk4 + 0][xm] = xa.x; xs[nb2][xk4 + 1][xm] = xa.y;
                    xs[nb2][xk4 + 2][xm] = xa.z; xs[nb2][xk4 + 3][xm] = xa.w;
                    xs[nb2][xk4 + 16][xm] = xb.x; xs[nb2][xk4 + 17][xm] = xb.y;
                    xs[nb2][xk4 + 18][xm] = xb.z; xs[nb2][xk4 + 19][xm] = xb.w;
                    *(float4*)&WS(nb2, wk +  0, wc4 * 4) = wv0;
                    *(float4*)&WS(nb2, wk +  8, wc4 * 4) = wv1;
                    *(float4*)&WS(nb2, wk + 16, wc4 * 4) = wv2;
                    *(float4*)&WS(nb2, wk + 24, wc4 * 4) = wv3;
                    __syncthreads();
                    buf = nb2;
                }
            }

            if (!gates) {
                const int gcolS = (n0t >> 4) * 256 + u0 + (n0t & 15);
#pragma unroll
                for (int a = 0; a < 4; a++) {
                    __stcg((float4*)(p_out + (size_t)(b0r + m0 + a) * 1024 + gcolS),
                           make_float4(acc[a][0], acc[a][1], acc[a][2], acc[a][3]));
                }
            } else {
                // ---- prefetch er/c with epilogue thread mapping BEFORE the zt exchange ----
                const int uu = tid & 15;
                const int bq = tid >> 4;
                const int colu = u0 + uu;
                const float* zxbase = (L == 0) ? g_zx0 : (L == 1) ? g_zx1 : g_zx2;

                float e0[4], e1[4], e2[4], e3[4], cold[4];
                bool act[4];
#pragma unroll
                for (int q = 0; q < 4; q++) {
                    const int bl = bq + 8 * q;
                    const int j = b0r + bl;
                    act[q] = (t < lens_s[L * Bc + j]);
                    if (act[q]) {
                        const float* er;
                        if (kind == 0)
                            er = zxbase + ((size_t)perm_s[L * Bc + j] * Ts + t) * 1024;
                        else
                            er = extra + (size_t)j * 1024;
                        e0[q] = __ldcg(&er[colu]);
                        e1[q] = __ldcg(&er[256 + colu]);
                        e2[q] = __ldcg(&er[512 + colu]);
                        e3[q] = __ldcg(&er[768 + colu]);
                        cold[q] = __ldcg(&c[j * Uc + colu]);
                    }
                }

                __syncthreads();
                float* zt = ws_raw;
#pragma unroll
                for (int cc = 0; cc < 4; cc++)
#pragma unroll
                    for (int a = 0; a < 4; a++)
                        zt[(n0t + cc) * 33 + (m0 + a)] = acc[a][cc];
                __syncthreads();

                const float bi = bias[colu];
                const float bj = bias[256 + colu];
                const float bf = bias[512 + colu];
                const float bo = bias[768 + colu];

#pragma unroll
                for (int q = 0; q < 4; q++) {
                    if (act[q]) {
                        const int bl = bq + 8 * q;
                        const int j = b0r + bl;
                        const int gidx = j * Uc + colu;
                        float g0 = zt[(  0 + uu) * 33 + bl] + bi + e0[q];
                        float g1 = zt[( 16 + uu) * 33 + bl] + bj + e1[q];
                        float g2 = zt[( 32 + uu) * 33 + bl] + bf + e2[q];
                        float g3 = zt[( 48 + uu) * 33 + bl] + bo + e3[q];
                        const float cn = cold[q] * sigm(g2 + 1.0f)
                                       + sigm(g0) * tanh_(g1);
                        const float hn = tanh_(cn) * sigm(g3);
                        __stcg(&c[gidx], cn);
                        __stcg(&h_out[gidx], hn);
                    }
                }
            }
        }

        __syncthreads();
        __threadfence();
        if (tid == 0) {
            atomicAdd(&g_bar, 1u);
            const unsigned target = (unsigned)NBLK * (unsigned)(i + 1);
            volatile unsigned* vb = &g_bar;
            while (*vb < target) __nanosleep(32);
        }
        __syncthreads();
    }
#undef WS
}

// ---------------- x-projection precompute (3-job batched, masked-block skip) ----------------
struct XJob { const float* x; const int* ids; const float* tab;
              const float* W; float* zx; const int* len; int rows, Din, T; };
struct XJobs { XJob j[3]; };

__global__ void xproj_kernel(XJobs jobs) {
    const XJob J = jobs.j[blockIdx.y];
    const int bm = blockIdx.x % 384;
    const int bn = blockIdx.x / 384;
    const int r0 = bm * 32;
    if (r0 >= J.rows) return;
    const int tid = threadIdx.x;

    int pred = 0;
    if (tid < 32) {
        const int r = r0 + tid;
        const int bb = r / J.T;
        const int tt = r - bb * J.T;
        pred = (tt < J.len[bb]);
    }
    if (!__syncthreads_or(pred)) return;

    const int n0 = bn * 128;
    __shared__ __align__(16) float xs[32][36];
    __shared__ __align__(16) float ws[32][128];
    const int mi = tid & 7, ni = tid >> 3;
    const int m0 = mi * 4, n0t = ni * 4;
    const int xm = tid >> 3, xk = (tid & 7) * 4;
    const int wc = (tid & 31) * 4, wk = tid >> 5;

    float acc[4][4];
#pragma unroll
    for (int a = 0; a < 4; a++)
#pragma unroll
        for (int b = 0; b < 4; b++) acc[a][b] = 0.0f;

    const int r = r0 + xm;
    const float* srow = J.ids ? (J.tab + (size_t)J.ids[r] * J.Din)
                              : (J.x + (size_t)r * J.Din);

    const int nk = (J.Din + 31) >> 5;
    for (int kt = 0; kt < nk; kt++) {
        const int k0 = kt * 32;
        __syncthreads();
#pragma unroll
        for (int j = 0; j < 4; j++) {
            const int k = k0 + xk + j;
            xs[xk + j][xm] = (k < J.Din) ? srow[k] : 0.0f;
        }
#pragma unroll
        for (int q = 0; q < 4; q++) {
            const int kk = wk + 8 * q, k = k0 + kk;
            float4 wv = make_float4(0.f, 0.f, 0.f, 0.f);
            if (k < J.Din)
                wv = *(const float4*)(J.W + (size_t)k * 1024 + n0 + wc);
            *(float4*)&ws[kk][wc] = wv;
        }
        __syncthreads();
#pragma unroll 8
        for (int kk = 0; kk < 32; kk++) {
            const float4 x = *(const float4*)&xs[kk][m0];
            const float4 w = *(const float4*)&ws[kk][n0t];
            acc[0][0] = fmaf(x.x, w.x, acc[0][0]);
            acc[0][1] = fmaf(x.x, w.y, acc[0][1]);
            acc[0][2] = fmaf(x.x, w.z, acc[0][2]);
            acc[0][3] = fmaf(x.x, w.w, acc[0][3]);
            acc[1][0] = fmaf(x.y, w.x, acc[1][0]);
            acc[1][1] = fmaf(x.y, w.y, acc[1][1]);
            acc[1][2] = fmaf(x.y, w.z, acc[1][2]);
            acc[1][3] = fmaf(x.y, w.w, acc[1][3]);
            acc[2][0] = fmaf(x.z, w.x, acc[2][0]);
            acc[2][1] = fmaf(x.z, w.y, acc[2][1]);
            acc[2][2] = fmaf(x.z, w.z, acc[2][2]);
            acc[2][3] = fmaf(x.z, w.w, acc[2][3]);
            acc[3][0] = fmaf(x.w, w.x, acc[3][0]);
            acc[3][1] = fmaf(x.w, w.y, acc[3][1]);
            acc[3][2] = fmaf(x.w, w.z, acc[3][2]);
            acc[3][3] = fmaf(x.w, w.w, acc[3][3]);
        }
    }
#pragma unroll
    for (int a = 0; a < 4; a++) {
        *(float4*)(J.zx + (size_t)(r0 + m0 + a) * 1024 + n0 + n0t) =
            make_float4(acc[a][0], acc[a][1], acc[a][2], acc[a][3]);
    }
}

// ---------------- embedding v3 (unchanged) ----------------
__global__ void __launch_bounds__(128) embed_kernel(
    const int* __restrict__ word_ids,
    const int* __restrict__ pos_ids,
    const float* __restrict__ w_emb,
    const float* __restrict__ p_emb,
    const float* __restrict__ W,
    const float* __restrict__ bias,
    float* __restrict__ out,
    int nrows,
    const int* __restrict__ len,
    int per_b, int per_item)
{
    const int r0 = blockIdx.x * 8;
    {
        const int b = r0 / per_b;
        const int item = (r0 - b * per_b) / per_item;
        if (item >= len[b]) return;
    }
    __shared__ __align__(16) float xs[EDINc][10];
    __shared__ int wid_s[8], pid_s[8];
    const int tid = threadIdx.x;

    if (tid < 8) {
        int row = r0 + tid;
        wid_s[tid] = (row < nrows) ? word_ids[row] : 0;
        pid_s[tid] = (row < nrows) ? pos_ids[row] : 0;
    }
    __syncthreads();

    for (int idx = tid; idx < 8 * EDINc; idx += 128) {
        int r = idx / EDINc, k = idx - r * EDINc;
        float v;
        if (k < WDIMc) v = w_emb[wid_s[r] * WDIMc + k];
        else           v = p_emb[pid_s[r] * POSDc + (k - WDIMc)];
        xs[k][r] = v;
    }
    __syncthreads();

    const int ri = tid >> 5;
    const int s0 = 2 * ri;
    const int n0 = (tid & 31) * 4;
    const float4 bv = *(const float4*)(bias + n0);
    const float* Wn = W + n0;

    float a00 = 0.f, a01 = 0.f, a02 = 0.f, a03 = 0.f;
    float a10 = 0.f, a11 = 0.f, a12 = 0.f, a13 = 0.f;

    float4 w0 = *(const float4*)(Wn + 0 * FCc);
    float4 w1 = *(const float4*)(Wn + 1 * FCc);
    float4 w2 = *(const float4*)(Wn + 2 * FCc);
    float4 w3 = *(const float4*)(Wn + 3 * FCc);
#pragma unroll 1
    for (int k = 0; k < 348; k += 4) {
        float4 p0, p1, p2, p3;
        p0 = (k + 4 < EDINc) ? *(const float4*)(Wn + (size_t)(k + 4) * FCc) : w0;
        p1 = (k + 5 < EDINc) ? *(const float4*)(Wn + (size_t)(k + 5) * FCc) : w1;
        p2 = (k + 6 < EDINc) ? *(const float4*)(Wn + (size_t)(k + 6) * FCc) : w2;
        p3 = (k + 7 < EDINc) ? *(const float4*)(Wn + (size_t)(k + 7) * FCc) : w3;
        const float2 x0 = *(const float2*)&xs[k + 0][s0];
        const float2 x1 = *(const float2*)&xs[k + 1][s0];
        const float2 x2 = *(const float2*)&xs[k + 2][s0];
        const float2 x3 = *(const float2*)&xs[k + 3][s0];
        a00 = fmaf(x0.x, w0.x, a00); a01 = fmaf(x0.x, w0.y, a01);
        a02 = fmaf(x0.x, w0.z, a02); a03 = fmaf(x0.x, w0.w, a03);
        a10 = fmaf(x0.y, w0.x, a10); a11 = fmaf(x0.y, w0.y, a11);
        a12 = fmaf(x0.y, w0.z, a12); a13 = fmaf(x0.y, w0.w, a13);
        a00 = fmaf(x1.x, w1.x, a00); a01 = fmaf(x1.x, w1.y, a01);
        a02 = fmaf(x1.x, w1.z, a02); a03 = fmaf(x1.x, w1.w, a03);
        a10 = fmaf(x1.y, w1.x, a10); a11 = fmaf(x1.y, w1.y, a11);
        a12 = fmaf(x1.y, w1.z, a12); a13 = fmaf(x1.y, w1.w, a13);
        a00 = fmaf(x2.x, w2.x, a00); a01 = fmaf(x2.x, w2.y, a01);
        a02 = fmaf(x2.x, w2.z, a02); a03 = fmaf(x2.x, w2.w, a03);
        a10 = fmaf(x2.y, w2.x, a10); a11 = fmaf(x2.y, w2.y, a11);
        a12 = fmaf(x2.y, w2.z, a12); a13 = fmaf(x2.y, w2.w, a13);
        a00 = fmaf(x3.x, w3.x, a00); a01 = fmaf(x3.x, w3.y, a01);
        a02 = fmaf(x3.x, w3.z, a02); a03 = fmaf(x3.x, w3.w, a03);
        a10 = fmaf(x3.y, w3.x, a10); a11 = fmaf(x3.y, w3.y, a11);
        a12 = fmaf(x3.y, w3.z, a12); a13 = fmaf(x3.y, w3.w, a13);
        w0 = p0; w1 = p1; w2 = p2; w3 = p3;
    }
    {
        const float2 x0 = *(const float2*)&xs[348][s0];
        const float2 x1 = *(const float2*)&xs[349][s0];
        a00 = fmaf(x0.x, w0.x, a00); a01 = fmaf(x0.x, w0.y, a01);
        a02 = fmaf(x0.x, w0.z, a02); a03 = fmaf(x0.x, w0.w, a03);
        a10 = fmaf(x0.y, w0.x, a10); a11 = fmaf(x0.y, w0.y, a11);
        a12 = fmaf(x0.y, w0.z, a12); a13 = fmaf(x0.y, w0.w, a13);
        a00 = fmaf(x1.x, w1.x, a00); a01 = fmaf(x1.x, w1.y, a01);
        a02 = fmaf(x1.x, w1.z, a02); a03 = fmaf(x1.x, w1.w, a03);
        a10 = fmaf(x1.y, w1.x, a10); a11 = fmaf(x1.y, w1.y, a11);
        a12 = fmaf(x1.y, w1.z, a12); a13 = fmaf(x1.y, w1.w, a13);
    }

    const int rowA = r0 + s0, rowB = r0 + s0 + 1;
    if (rowA < nrows)
        *(float4*)(out + (size_t)rowA * FCc + n0) = make_float4(
            fmaxf(a00 + bv.x, 0.f), fmaxf(a01 + bv.y, 0.f),
            fmaxf(a02 + bv.z, 0.f), fmaxf(a03 + bv.w, 0.f));
    if (rowB < nrows)
        *(float4*)(out + (size_t)rowB * FCc + n0) = make_float4(
            fmaxf(a10 + bv.x, 0.f), fmaxf(a11 + bv.y, 0.f),
            fmaxf(a12 + bv.z, 0.f), fmaxf(a13 + bv.w, 0.f));
}

// ---------------- compose v4 (reverted: 128 threads, 2seq x 4col, depth-8 prefetch) ----------------
__global__ void __launch_bounds__(128) compose_kernel(
    const int* __restrict__ comp_word_id,
    const float* __restrict__ comp_emb,
    const int* __restrict__ comp_action_id,
    const int* __restrict__ comp_action_len,
    const float* __restrict__ a_emb,
    const float* __restrict__ rec_W,
    const float* __restrict__ rec_b,
    const int* __restrict__ stack_len,
    float* __restrict__ stack_emb)
{
    const int seq0 = blockIdx.x * CSEQ;
    {
        const int b = seq0 / STKc;
        const int stk0 = seq0 - b * STKc;
        if (stk0 >= stack_len[b]) return;
    }
    const int tid = threadIdx.x;

    __shared__ float vals[8][CSEQ][FCc];
    __shared__ __align__(16) float xs[RDINc][10];
    __shared__ int wid[CSEQ][16];
    __shared__ int act[CSEQ][8];
    __shared__ int alen[CSEQ];
    __shared__ signed char ihs[CSEQ][8], idds[CSEQ][8];

    {
        const int ss = tid >> 4, slot = tid & 15;
        wid[ss][slot] = comp_word_id[(seq0 + ss) * 16 + slot];
        if (tid < CSEQ * 8) {
            const int s2 = tid >> 3, n = tid & 7;
            act[s2][n] = comp_action_id[(seq0 + s2) * 8 + n];
        }
        if (tid < CSEQ) alen[tid] = comp_action_len[seq0 + tid];
    }
    __syncthreads();
    if (tid < CSEQ * 8) {
        const int ss = tid >> 3, n = tid & 7;
        const int hn = wid[ss][2 * n], dn = wid[ss][2 * n + 1];
        int ih = -1, idd = -1;
        for (int m = 0; m < n; m++) {
            const int hm = wid[ss][2 * m];
            if (hm == hn) ih = m;
            if (hm == dn) idd = m;
        }
        ihs[ss][n] = (signed char)ih;
        idds[ss][n] = (signed char)idd;
    }
    __syncthreads();

    const int mi = tid & 3,  ni = tid >> 2;
    const int s0 = mi * 2,   n0 = ni * 4;
    const float4 bn = *(const float4*)(rec_b + n0);
    const float* Wn = rec_W + n0;

    for (int n = 0; n < 8; n++) {
#pragma unroll
        for (int ss = 0; ss < CSEQ; ss++) {
            const int ih = ihs[ss][n], idd = idds[ss][n];
            const int an = act[ss][n];
#pragma unroll
            for (int j = 0; j < 3; j++) {
                const int k = tid + j * 128;
                if (k < RDINc) {
                    float v;
                    if (k < FCc) {
                        v = (ih >= 0) ? vals[ih][ss][k]
                                      : comp_emb[((size_t)(seq0 + ss) * 16 + 2 * n) * FCc + k];
                    } else if (k < FCc + CADc) {
                        v = a_emb[an * CADc + (k - FCc)];
                    } else {
                        const int kk = k - (FCc + CADc);
                        v = (idd >= 0) ? vals[idd][ss][kk]
                                       : comp_emb[((size_t)(seq0 + ss) * 16 + 2 * n + 1) * FCc + kk];
                    }
                    xs[k][ss] = v;
                }
            }
        }
        __syncthreads();

        float a00 = 0.f, a01 = 0.f, a02 = 0.f, a03 = 0.f;
        float a10 = 0.f, a11 = 0.f, a12 = 0.f, a13 = 0.f;

        float4 w[8];
#pragma unroll
        for (int j = 0; j < 8; j++)
            w[j] = *(const float4*)(Wn + (size_t)j * FCc);

#pragma unroll 1
        for (int k = 0; k < 296; k += 8) {
            float4 p[8];
#pragma unroll
            for (int j = 0; j < 8; j++)
                p[j] = *(const float4*)(Wn + (size_t)(k + 8 + j) * FCc);
#pragma unroll
            for (int j = 0; j < 8; j++) {
                const float2 x = *(const float2*)&xs[k + j][s0];
                a00 = fmaf(x.x, w[j].x, a00); a01 = fmaf(x.x, w[j].y, a01);
                a02 = fmaf(x.x, w[j].z, a02); a03 = fmaf(x.x, w[j].w, a03);
                a10 = fmaf(x.y, w[j].x, a10); a11 = fmaf(x.y, w[j].y, a11);
                a12 = fmaf(x.y, w[j].z, a12); a13 = fmaf(x.y, w[j].w, a13);
            }
#pragma unroll
            for (int j = 0; j < 8; j++) w[j] = p[j];
        }
#pragma unroll
        for (int j = 0; j < 8; j++) {
            const float2 x = *(const float2*)&xs[296 + j][s0];
            a00 = fmaf(x.x, w[j].x, a00); a01 = fmaf(x.x, w[j].y, a01);
            a02 = fmaf(x.x, w[j].z, a02); a03 = fmaf(x.x, w[j].w, a03);
            a10 = fmaf(x.y, w[j].x, a10); a11 = fmaf(x.y, w[j].y, a11);
            a12 = fmaf(x.y, w[j].z, a12); a13 = fmaf(x.y, w[j].w, a13);
        }
#pragma unroll
        for (int j = 0; j < 2; j++) {
            const float4 wt = *(const float4*)(Wn + (size_t)(304 + j) * FCc);
            const float2 x = *(const float2*)&xs[304 + j][s0];
            a00 = fmaf(x.x, wt.x, a00); a01 = fmaf(x.x, wt.y, a01);
            a02 = fmaf(x.x, wt.z, a02); a03 = fmaf(x.x, wt.w, a03);
            a10 = fmaf(x.y, wt.x, a10); a11 = fmaf(x.y, wt.y, a11);
            a12 = fmaf(x.y, wt.z, a12); a13 = fmaf(x.y, wt.w, a13);
        }

        *(float4*)&vals[n][s0 + 0][n0] = make_float4(
            tanhf(a00 + bn.x), tanhf(a01 + bn.y), tanhf(a02 + bn.z), tanhf(a03 + bn.w));
        *(float4*)&vals[n][s0 + 1][n0] = make_float4(
            tanhf(a10 + bn.x), tanhf(a11 + bn.y), tanhf(a12 + bn.z), tanhf(a13 + bn.w));
        __syncthreads();
    }

#pragma unroll
    for (int ss = 0; ss < CSEQ; ss++) {
        const int al = alen[ss];
        const float v = (al == 0)
            ? comp_emb[(size_t)(seq0 + ss) * 16 * FCc + tid]
            : vals[al - 1][ss][tid];
        stack_emb[(size_t)(seq0 + ss) * FCc + tid] = v;
    }
}

// ---------------- output head ----------------
__global__ void final_kernel(const int* __restrict__ l0,
                             const int* __restrict__ l1,
                             const int* __restrict__ l2,
                             const float* __restrict__ fW,
                             const float* __restrict__ fb,
                             float* __restrict__ out) {
    const int b = blockIdx.x;
    const int tid = threadIdx.x;
    __shared__ float hcat[3 * Uc];
    for (int idx = tid; idx < 3 * Uc; idx += 128) {
        const int L = idx >> 8;
        const int col = idx & 255;
        const int len = ((L == 0) ? l0 : (L == 1) ? l1 : l2)[b];
        const int j = g_inv[L][b];
        hcat[idx] = g_h1[L][(len - 1) & 1][j * Uc + col];
    }
    __syncthreads();
    if (tid < NOUTc) {
        float acc = fb[tid];
#pragma unroll 2
        for (int k = 0; k < 3 * Uc; k++) acc = fmaf(hcat[k], fW[k * NOUTc + tid], acc);
        out[b * NOUTc + tid] = acc;
    }
}

// ---------------- host driver (single stream) ----------------
extern "C" void kernel_launch(void* const* d_in, const int* in_sizes, int n_in,
                              void* d_out, int out_size) {
    const int*   buff_word_id   = (const int*)d_in[0];
    const int*   buff_pos_id    = (const int*)d_in[1];
    const int*   comp_word_id   = (const int*)d_in[2];
    const int*   comp_pos_id    = (const int*)d_in[3];
    const int*   comp_action_id = (const int*)d_in[4];
    const int*   comp_action_len= (const int*)d_in[5];
    const int*   history_action_id = (const int*)d_in[6];
    const int*   stack_length   = (const int*)d_in[7];
    const int*   buff_length    = (const int*)d_in[8];
    const int*   history_action_length = (const int*)d_in[9];
    const float* p_emb      = (const float*)d_in[10];
    const float* comp_a_emb = (const float*)d_in[11];
    const float* hist_a_emb = (const float*)d_in[12];
    const float* w_emb      = (const float*)d_in[13];
    const float* emb_W      = (const float*)d_in[14];
    const float* emb_b      = (const float*)d_in[15];
    const float* rec_W      = (const float*)d_in[16];
    const float* rec_b      = (const float*)d_in[17];
    const float* W0s[3] = { (const float*)d_in[18], (const float*)d_in[22], (const float*)d_in[26] };
    const float* b0s[3] = { (const float*)d_in[19], (const float*)d_in[23], (const float*)d_in[27] };
    const float* W1s[3] = { (const float*)d_in[20], (const float*)d_in[24], (const float*)d_in[28] };
    const float* b1s[3] = { (const float*)d_in[21], (const float*)d_in[25], (const float*)d_in[29] };
    const float* fW  = (const float*)d_in[30];
    const float* fb  = (const float*)d_in[31];
    float* out = (float*)d_out;

    float *buff_emb_p, *comp_emb_p, *stack_emb_p;
    float *zx0_p, *zx1_p, *zx2_p;
    float *c0_p, *c1_p, *h0_p, *h1_p;
    unsigned* bar_p;
    cudaGetSymbolAddress((void**)&buff_emb_p,  g_buff_emb);
    cudaGetSymbolAddress((void**)&comp_emb_p,  g_comp_emb);
    cudaGetSymbolAddress((void**)&stack_emb_p, g_stack_emb);
    cudaGetSymbolAddress((void**)&zx0_p, g_zx0);
    cudaGetSymbolAddress((void**)&zx1_p, g_zx1);
    cudaGetSymbolAddress((void**)&zx2_p, g_zx2);
    cudaGetSymbolAddress((void**)&c0_p, g_c0);
    cudaGetSymbolAddress((void**)&c1_p, g_c1);
    cudaGetSymbolAddress((void**)&h0_p, g_h0);
    cudaGetSymbolAddress((void**)&h1_p, g_h1);
    cudaGetSymbolAddress((void**)&bar_p, g_bar);

    const size_t SB = (size_t)Bc * Uc;

    cudaMemsetAsync(bar_p, 0, sizeof(unsigned));
    cudaMemsetAsync(c0_p, 0, 3 * SB * sizeof(float));
    cudaMemsetAsync(c1_p, 0, 3 * SB * sizeof(float));
    cudaMemsetAsync(h0_p, 0, 3 * 2 * SB * sizeof(float));
    cudaMemsetAsync(h1_p, 0, 3 * 2 * SB * sizeof(float));

    // length sort + per-step active counts
    sort_kernel<<<3, 128>>>(stack_length, buff_length, history_action_length);

    // embeddings (dead-block skipping)
    const int nbuff = Bc * BUFFc;
    embed_kernel<<<(nbuff + 7) / 8, 128>>>(buff_word_id, buff_pos_id, w_emb, p_emb,
                                           emb_W, emb_b, buff_emb_p, nbuff,
                                           buff_length, BUFFc, 1);
    const int ncomp = Bc * STKc * 16;
    embed_kernel<<<(ncomp + 7) / 8, 128>>>(comp_word_id, comp_pos_id, w_emb, p_emb,
                                           emb_W, emb_b, comp_emb_p, ncomp,
                                           stack_length, STKc * 16, 16);

    // recursive compose (v4)
    compose_kernel<<<Bc * STKc / CSEQ, 128>>>(comp_word_id, comp_emb_p,
                                              comp_action_id, comp_action_len,
                                              comp_a_emb, rec_W, rec_b,
                                              stack_length, stack_emb_p);

    // x-projections for layer0
    {
        XJobs xj;
        xj.j[0] = XJob{ stack_emb_p, nullptr, nullptr, W0s[0], zx0_p,
                        stack_length, Bc * STKc,  FCc, STKc };
        xj.j[1] = XJob{ buff_emb_p,  nullptr, nullptr, W0s[1], zx1_p,
                        buff_length, Bc * BUFFc, FCc, BUFFc };
        xj.j[2] = XJob{ nullptr, history_action_id, hist_a_emb, W0s[2], zx2_p,
                        history_action_length, Bc * HISTc, 50, HISTc };
        xproj_kernel<<<dim3(384 * 8, 3), 256>>>(xj);
    }

    // persistent fused loop
    {
        PParams P;
        for (int L = 0; L < 3; L++) {
            const int din = (L == 2) ? 50 : FCc;
            P.W0h[L] = W0s[L] + (size_t)din * 1024;
            P.b0[L]  = b0s[L];
            P.W1a[L] = W1s[L];
            P.W1b[L] = W1s[L] + (size_t)256 * 1024;
            P.b1[L]  = b1s[L];
        }
        lstm_loop_kernel<<<NBLK, 128>>>(P);
    }

    // output head
    final_kernel<<<Bc, 128>>>(stack_length, buff_length, history_action_length,
                              fW, fb, out);
}